// round 10
// baseline (speedup 1.0000x reference)
#include <cuda_runtime.h>
#include <cuda_fp16.h>
#include <cstdint>

// Dims fixed by setup_inputs: B=256, Q=256, S=512, D=1024
#define NB 256
#define NQ 256
#define NS 512
#define ND 1024
#define EPS 1e-8f
#define SLOPE 0.1f
#define SMOOTH 9.0f

__device__ float g_invnorm[NB * NS];
__device__ float g_invden[NB * NQ];
__device__ float g_part[2][NB * NS];  // per-(q-block) partial sum of squares

// ---------------------------------------------------------------------------
// helpers
// ---------------------------------------------------------------------------
__device__ __forceinline__ void ldsm4(uint32_t* r, uint32_t addr) {
  asm volatile("ldmatrix.sync.aligned.m8n8.x4.shared.b16 {%0,%1,%2,%3}, [%4];"
               : "=r"(r[0]), "=r"(r[1]), "=r"(r[2]), "=r"(r[3]) : "r"(addr));
}
__device__ __forceinline__ void ldsm4t(uint32_t* r, uint32_t addr) {
  asm volatile("ldmatrix.sync.aligned.m8n8.x4.trans.shared.b16 {%0,%1,%2,%3}, [%4];"
               : "=r"(r[0]), "=r"(r[1]), "=r"(r[2]), "=r"(r[3]) : "r"(addr));
}
__device__ __forceinline__ void mma16816(float* c, const uint32_t* a, const uint32_t* b) {
  asm volatile(
      "mma.sync.aligned.m16n8k16.row.col.f32.f16.f16.f32 "
      "{%0,%1,%2,%3}, {%4,%5,%6,%7}, {%8,%9}, {%0,%1,%2,%3};"
      : "+f"(c[0]), "+f"(c[1]), "+f"(c[2]), "+f"(c[3])
      : "r"(a[0]), "r"(a[1]), "r"(a[2]), "r"(a[3]), "r"(b[0]), "r"(b[1]));
}
__device__ __forceinline__ uint32_t smem_u32(const void* p) {
  uint32_t a;
  asm("{ .reg .u64 t; cvta.to.shared.u64 t, %1; cvt.u32.u64 %0, t; }" : "=r"(a) : "l"(p));
  return a;
}
__device__ __forceinline__ void cpa16(uint32_t dst, const void* src) {
  asm volatile("cp.async.cg.shared.global [%0], [%1], 16;" :: "r"(dst), "l"(src));
}
#define CP_COMMIT() asm volatile("cp.async.commit_group;" ::: "memory")
#define CP_WAIT1() asm volatile("cp.async.wait_group 1;" ::: "memory")
// fp32x4 -> fp16x4 (RN)
__device__ __forceinline__ uint2 cvt4h(float4 v) {
  __half2 h0 = __floats2half2_rn(v.x, v.y);
  __half2 h1 = __floats2half2_rn(v.z, v.w);
  uint2 h;
  h.x = *(uint32_t*)&h0;
  h.y = *(uint32_t*)&h1;
  return h;
}

// ===========================================================================
// GEMM1: P[s][q] = leakyrelu( sum_d ctx[s][d]*qry[q][d] ), fp16 x fp16 / fp32 acc.
// m=s (A=ctx), n=q (B=qry), k=d. CTA 128x128, K-chunk 32, 8 warps (2m x 4n).
// 3-stage cp.async fp32 staging -> in-smem cvt (interleaved with mma) ->
// double-buffered fp16 tiles. One __syncthreads per chunk.
// ===========================================================================
#define P1 40      // fp16 smem row stride (half)
#define F1 40      // fp32 stage row stride (float)
#define H_MAT1 (128 * P1 * 2)       // 10240 B
#define H_BUF1 (2 * H_MAT1)         // 20480 B (A then B)
#define F_MAT1 (128 * F1 * 4)       // 20480 B
#define F_STG1 (2 * F_MAT1)         // 40960 B (A then B)
#define OFF_F1 (2 * H_BUF1)         // 40960
#define OFF_SRED1 (OFF_F1 + 3 * F_STG1)  // 163840
#define SMEM_G1 (OFF_SRED1 + 4 * 128 * 4)  // 165888
#define NCH1 (ND / 32)  // 32

__global__ __launch_bounds__(256) void k_scores_mma(
    const float* __restrict__ qry, const float* __restrict__ ctx,
    float* __restrict__ P) {
  extern __shared__ __align__(16) char sm[];
  const uint32_t sb = smem_u32(sm);
  float* sred = (float*)(sm + OFF_SRED1);

  const int t = threadIdx.x, w = t >> 5, lane = t & 31;
  const int b = blockIdx.z, qblk = blockIdx.x, q0 = qblk * 128, s0 = blockIdx.y * 128;
  const int warp_m = w >> 2, warp_n = w & 3;

  const float* Abase = ctx + ((size_t)(b * NS + s0)) * ND;  // rows = s
  const float* Bbase = qry + ((size_t)(b * NQ + q0)) * ND;  // rows = q

  // cp.async mapping: 1024 16B tasks per matrix -> 4 per thread per matrix
  // id = t + 256*i : row = id>>3 (0..127), seg = id&7, col = seg*4 floats
  // cvt mapping (R9-verified, octet=fixed lr -> conflict-free):
  const int lr = lane >> 3, lc8 = lane & 7;
  const int ccol = lc8 * 4;

  // ldmatrix lane addressing (non-trans) — verified mapping
  const int g = lane >> 3, r8 = lane & 7;
  const int a_row = (g & 1) * 8 + r8, a_col = (g >> 1) * 8;
  const int b_row = (g >> 1) * 8 + r8, b_col = (g & 1) * 8;

  float acc[4][4][4];
#pragma unroll
  for (int i = 0; i < 4; i++)
#pragma unroll
    for (int j = 0; j < 4; j++)
#pragma unroll
      for (int k = 0; k < 4; k++) acc[i][j][k] = 0.0f;

#define ISSUE1(st, kc)                                                        \
  {                                                                           \
    const uint32_t base = sb + OFF_F1 + (st) * F_STG1;                        \
    _Pragma("unroll") for (int i = 0; i < 4; i++) {                           \
      const int id = t + 256 * i;                                             \
      const int row = id >> 3, col = (id & 7) * 4;                            \
      const uint32_t doff = (uint32_t)(row * F1 + col) * 4u;                  \
      cpa16(base + doff, Abase + (size_t)row * ND + (kc) + col);              \
      cpa16(base + F_MAT1 + doff, Bbase + (size_t)row * ND + (kc) + col);     \
    }                                                                         \
  }

#define CVT1(st, hb)                                                          \
  {                                                                           \
    const char* fbase = sm + OFF_F1 + (st) * F_STG1;                          \
    char* hbase = sm + (hb) * H_BUF1;                                         \
    _Pragma("unroll") for (int r4 = 0; r4 < 4; r4++) {                        \
      const int row = r4 * 32 + w * 4 + lr;                                   \
      float4 va = *(const float4*)(fbase + (size_t)(row * F1 + ccol) * 4);    \
      float4 vb = *(const float4*)(fbase + F_MAT1 + (size_t)(row * F1 + ccol) * 4); \
      *(uint2*)(hbase + (size_t)(row * P1 + ccol) * 2) = cvt4h(va);           \
      *(uint2*)(hbase + H_MAT1 + (size_t)(row * P1 + ccol) * 2) = cvt4h(vb);  \
    }                                                                         \
  }

  // prologue: fill stages 0,1; convert chunk 0
  ISSUE1(0, 0);
  CP_COMMIT();
  ISSUE1(1, 32);
  CP_COMMIT();
  CP_WAIT1();
  __syncthreads();
  CVT1(0, 0);

  int stI = 2;  // stage receiving chunk c+2
  int stC = 1;  // stage holding chunk c+1
  for (int c = 0; c < NCH1; c++) {
    if (c + 2 < NCH1) ISSUE1(stI, (c + 2) * 32);
    CP_COMMIT();
    CP_WAIT1();  // chunk c+1 resident (thread-local)
    __syncthreads();  // cross-thread: cvt(c) + chunk c+1 visible; stage stI free

    if (c + 1 < NCH1) CVT1(stC, (c + 1) & 1);  // interleaves with mma below

    const uint32_t aH = sb + (c & 1) * H_BUF1;
    const uint32_t bH = aH + H_MAT1;
#pragma unroll
    for (int kk = 0; kk < 32; kk += 16) {
      uint32_t bq[2][4];
#pragma unroll
      for (int np = 0; np < 2; np++) {
        const uint32_t off = ((warp_n * 32 + np * 16 + b_row) * P1 + kk + b_col) * 2;
        ldsm4(bq[np], bH + off);
      }
#pragma unroll
      for (int mi = 0; mi < 4; mi++) {
        uint32_t ah[4];
        const uint32_t off = ((warp_m * 64 + mi * 16 + a_row) * P1 + kk + a_col) * 2;
        ldsm4(ah, aH + off);
#pragma unroll
        for (int nt = 0; nt < 4; nt++) {
          mma16816(acc[mi][nt], ah, &bq[nt >> 1][(nt & 1) * 2]);
        }
      }
    }
    stI = (stI == 2) ? 0 : stI + 1;
    stC = (stC == 2) ? 0 : stC + 1;
  }

  // epilogue: leaky relu, write P[s][q], accumulate row sums of squares
  const int gm = lane >> 2, tg = lane & 3;
  float* Pb = P + (size_t)b * NS * NQ;
  float rsum[4][2];
#pragma unroll
  for (int mi = 0; mi < 4; mi++) {
    rsum[mi][0] = 0.0f;
    rsum[mi][1] = 0.0f;
    const int sg = s0 + warp_m * 64 + mi * 16 + gm;
#pragma unroll
    for (int nt = 0; nt < 4; nt++) {
      const int qg = q0 + warp_n * 32 + nt * 8 + tg * 2;
      float* c = acc[mi][nt];
      float2 v0 = make_float2(c[0] > 0.f ? c[0] : SLOPE * c[0],
                              c[1] > 0.f ? c[1] : SLOPE * c[1]);
      float2 v1 = make_float2(c[2] > 0.f ? c[2] : SLOPE * c[2],
                              c[3] > 0.f ? c[3] : SLOPE * c[3]);
      *(float2*)(Pb + (size_t)sg * NQ + qg) = v0;
      *(float2*)(Pb + (size_t)(sg + 8) * NQ + qg) = v1;
      rsum[mi][0] += v0.x * v0.x + v0.y * v0.y;
      rsum[mi][1] += v1.x * v1.x + v1.y * v1.y;
    }
  }
  __syncthreads();  // smem reuse: stages done
#pragma unroll
  for (int mi = 0; mi < 4; mi++) {
#pragma unroll
    for (int h = 0; h < 2; h++) {
      float s = rsum[mi][h];
      s += __shfl_xor_sync(0xffffffffu, s, 1);
      s += __shfl_xor_sync(0xffffffffu, s, 2);
      if (tg == 0) sred[warp_n * 128 + warp_m * 64 + mi * 16 + h * 8 + gm] = s;
    }
  }
  __syncthreads();
  if (t < 128) {
    float s = sred[t] + sred[128 + t] + sred[256 + t] + sred[384 + t];
    g_part[qblk][(size_t)b * NS + s0 + t] = s;
  }
}

// ===========================================================================
// GEMM2: W[q][d] = sum_s attn[s][q]*ctx[s][d], fp16 x fp16 / fp32 acc.
// m=q (attn via ldsm.trans), n=d (ctx via ldsm.trans), k=s. Same pipeline.
// ===========================================================================
#define P2 136     // fp16 smem row stride (half)
#define F2 132     // fp32 stage row stride (float)
#define H_MAT2 (32 * P2 * 2)        // 8704 B
#define H_BUF2 (2 * H_MAT2)         // 17408 B
#define F_MAT2 (32 * F2 * 4)        // 16896 B
#define F_STG2 (2 * F_MAT2)         // 33792 B
#define OFF_F2 (2 * H_BUF2)         // 34816
#define SMEM_G2 (OFF_F2 + 3 * F_STG2)  // 136192
#define NCH2 (NS / 32)  // 16

__global__ __launch_bounds__(256) void k_weighted_mma(
    const float* __restrict__ attn, const float* __restrict__ ctx,
    float* __restrict__ W) {
  extern __shared__ __align__(16) char sm[];
  const uint32_t sb = smem_u32(sm);

  const int t = threadIdx.x, w = t >> 5, lane = t & 31;
  const int b = blockIdx.z, d0 = blockIdx.x * 128, q0 = blockIdx.y * 128;
  const int warp_m = w >> 2, warp_n = w & 3;

  const float* Ab = attn + (size_t)b * NS * NQ;
  const float* Bb = ctx + (size_t)b * NS * ND;

  const int lr = lane >> 3, lc8 = lane & 7;
  const int crow = w * 4 + lr;  // 0..31 for cvt

  // ldmatrix.trans lane addressing — verified mapping
  const int g = lane >> 3, r8 = lane & 7;
  const int a_k = (g >> 1) * 8 + r8, a_m = (g & 1) * 8;
  const int b_k = (g & 1) * 8 + r8, b_n = (g >> 1) * 8;

  float acc[4][4][4];
#pragma unroll
  for (int i = 0; i < 4; i++)
#pragma unroll
    for (int j = 0; j < 4; j++)
#pragma unroll
      for (int k = 0; k < 4; k++) acc[i][j][k] = 0.0f;

#define ISSUE2(st, sc)                                                        \
  {                                                                           \
    const uint32_t base = sb + OFF_F2 + (st) * F_STG2;                        \
    _Pragma("unroll") for (int i = 0; i < 4; i++) {                           \
      const int id = t + 256 * i;                                             \
      const int row = id >> 5, col = (id & 31) * 4;                           \
      const uint32_t doff = (uint32_t)(row * F2 + col) * 4u;                  \
      cpa16(base + doff, Ab + (size_t)((sc) + row) * NQ + q0 + col);          \
      cpa16(base + F_MAT2 + doff, Bb + (size_t)((sc) + row) * ND + d0 + col); \
    }                                                                         \
  }

#define CVT2(st, hb)                                                          \
  {                                                                           \
    const char* fbase = sm + OFF_F2 + (st) * F_STG2;                          \
    char* hbase = sm + (hb) * H_BUF2;                                         \
    _Pragma("unroll") for (int cr = 0; cr < 4; cr++) {                        \
      const int col = cr * 32 + lc8 * 4;                                      \
      float4 va = *(const float4*)(fbase + (size_t)(crow * F2 + col) * 4);    \
      float4 vb = *(const float4*)(fbase + F_MAT2 + (size_t)(crow * F2 + col) * 4); \
      *(uint2*)(hbase + (size_t)(crow * P2 + col) * 2) = cvt4h(va);           \
      *(uint2*)(hbase + H_MAT2 + (size_t)(crow * P2 + col) * 2) = cvt4h(vb);  \
    }                                                                         \
  }

  ISSUE2(0, 0);
  CP_COMMIT();
  ISSUE2(1, 32);
  CP_COMMIT();
  CP_WAIT1();
  __syncthreads();
  CVT2(0, 0);

  int stI = 2, stC = 1;
  for (int c = 0; c < NCH2; c++) {
    if (c + 2 < NCH2) ISSUE2(stI, (c + 2) * 32);
    CP_COMMIT();
    CP_WAIT1();
    __syncthreads();

    if (c + 1 < NCH2) CVT2(stC, (c + 1) & 1);

    const uint32_t aH = sb + (c & 1) * H_BUF2;
    const uint32_t bH = aH + H_MAT2;
#pragma unroll
    for (int kk = 0; kk < 32; kk += 16) {
      uint32_t bq[2][4];
#pragma unroll
      for (int np = 0; np < 2; np++) {
        const uint32_t off = ((kk + b_k) * P2 + warp_n * 32 + np * 16 + b_n) * 2;
        ldsm4t(bq[np], bH + off);
      }
#pragma unroll
      for (int mi = 0; mi < 4; mi++) {
        uint32_t ah[4];
        const uint32_t off = ((kk + a_k) * P2 + warp_m * 64 + mi * 16 + a_m) * 2;
        ldsm4t(ah, aH + off);
#pragma unroll
        for (int nt = 0; nt < 4; nt++) {
          mma16816(acc[mi][nt], ah, &bq[nt >> 1][(nt & 1) * 2]);
        }
      }
    }
    stI = (stI == 2) ? 0 : stI + 1;
    stC = (stC == 2) ? 0 : stC + 1;
  }

  const int gm = lane >> 2, tg = lane & 3;
  float* Wb = W + (size_t)b * NQ * ND;
#pragma unroll
  for (int mi = 0; mi < 4; mi++) {
    const int qg = q0 + warp_m * 64 + mi * 16 + gm;
#pragma unroll
    for (int nt = 0; nt < 4; nt++) {
      const int dg = d0 + warp_n * 32 + nt * 8 + tg * 2;
      float* c = acc[mi][nt];
      *(float2*)(Wb + (size_t)qg * ND + dg) = make_float2(c[0], c[1]);
      *(float2*)(Wb + (size_t)(qg + 8) * ND + dg) = make_float2(c[2], c[3]);
    }
  }
}

// ---------------------------------------------------------------------------
// Softmax chain: denom fuses the partial-norm combine (writes g_invnorm too)
// ---------------------------------------------------------------------------
__global__ __launch_bounds__(256) void k_denom(const float* __restrict__ P) {
  __shared__ float siv[NS];
  const int b = blockIdx.x;
  const int q = threadIdx.x;
  for (int s = q; s < NS; s += 256) {
    float v = 1.0f / (sqrtf(g_part[0][(size_t)b * NS + s] +
                            g_part[1][(size_t)b * NS + s]) + EPS);
    siv[s] = v;
    g_invnorm[(size_t)b * NS + s] = v;
  }
  __syncthreads();
  const float* Pb = P + (size_t)b * NS * NQ + q;
  float d0 = 0.f, d1 = 0.f, d2 = 0.f, d3 = 0.f;
#pragma unroll 4
  for (int s = 0; s < NS; s += 4) {
    d0 += __expf(SMOOTH * Pb[(size_t)(s + 0) * NQ] * siv[s + 0]);
    d1 += __expf(SMOOTH * Pb[(size_t)(s + 1) * NQ] * siv[s + 1]);
    d2 += __expf(SMOOTH * Pb[(size_t)(s + 2) * NQ] * siv[s + 2]);
    d3 += __expf(SMOOTH * Pb[(size_t)(s + 3) * NQ] * siv[s + 3]);
  }
  g_invden[b * NQ + q] = 1.0f / (d0 + d1 + d2 + d3);
}

__global__ __launch_bounds__(256) void k_final(float* __restrict__ P) {
  const size_t idx4 = (size_t)blockIdx.x * blockDim.x + threadIdx.x;
  const int q4 = (int)(idx4 & 63);
  const size_t row = idx4 >> 6;
  const int b = (int)(row >> 9);
  const float inv = g_invnorm[row];
  const float* id = g_invden + b * NQ + q4 * 4;
  float4 v = ((float4*)P)[idx4];
  v.x = __expf(SMOOTH * v.x * inv) * id[0];
  v.y = __expf(SMOOTH * v.y * inv) * id[1];
  v.z = __expf(SMOOTH * v.z * inv) * id[2];
  v.w = __expf(SMOOTH * v.w * inv) * id[3];
  ((float4*)P)[idx4] = v;
}

// ---------------------------------------------------------------------------
// d_out = [ weighted (B,Q,D) | attnT (B,S,Q) ]; attnT region doubles as
// scratch for the score matrix through the softmax chain.
// ---------------------------------------------------------------------------
extern "C" void kernel_launch(void* const* d_in, const int* in_sizes, int n_in,
                              void* d_out, int out_size) {
  const float* qry = (const float*)d_in[0];  // (B,Q,D)
  const float* ctx = (const float*)d_in[1];  // (B,S,D)
  float* W = (float*)d_out;                         // (B,Q,D)
  float* P = (float*)d_out + (size_t)NB * NQ * ND;  // (B,S,Q)

  cudaFuncSetAttribute(k_scores_mma, cudaFuncAttributeMaxDynamicSharedMemorySize, SMEM_G1);
  cudaFuncSetAttribute(k_weighted_mma, cudaFuncAttributeMaxDynamicSharedMemorySize, SMEM_G2);

  {
    dim3 g(NQ / 128, NS / 128, NB);  // (2, 4, 256)
    k_scores_mma<<<g, 256, SMEM_G1>>>(qry, ctx, P);
  }
  k_denom<<<NB, 256>>>(P);
  k_final<<<(size_t)NB * NS * NQ / 4 / 256, 256>>>(P);
  {
    dim3 g(ND / 128, NQ / 128, NB);  // (8, 2, 256)
    k_weighted_mma<<<g, 256, SMEM_G2>>>(P, ctx, W);
  }
}

// round 11
// speedup vs baseline: 1.5931x; 1.5931x over previous
#include <cuda_runtime.h>
#include <cuda_fp16.h>
#include <cstdint>

// Dims fixed by setup_inputs: B=256, Q=256, S=512, D=1024
#define NB 256
#define NQ 256
#define NS 512
#define EPS 1e-8f
#define ND 1024
#define SLOPE 0.1f
#define SMOOTH 9.0f

__device__ float g_invnorm[NB * NS];
__device__ float g_invden[NB * NQ];
__device__ float g_part[2][NB * NS];  // per-(q-block) partial sum of squares
__device__ __align__(16) __half g_ah[(size_t)NB * NS * NQ];  // fp16 attn (67MB)

// ---------------------------------------------------------------------------
// helpers
// ---------------------------------------------------------------------------
__device__ __forceinline__ void ldsm4(uint32_t* r, uint32_t addr) {
  asm volatile("ldmatrix.sync.aligned.m8n8.x4.shared.b16 {%0,%1,%2,%3}, [%4];"
               : "=r"(r[0]), "=r"(r[1]), "=r"(r[2]), "=r"(r[3]) : "r"(addr));
}
__device__ __forceinline__ void ldsm4t(uint32_t* r, uint32_t addr) {
  asm volatile("ldmatrix.sync.aligned.m8n8.x4.trans.shared.b16 {%0,%1,%2,%3}, [%4];"
               : "=r"(r[0]), "=r"(r[1]), "=r"(r[2]), "=r"(r[3]) : "r"(addr));
}
__device__ __forceinline__ void mma16816(float* c, const uint32_t* a, const uint32_t* b) {
  asm volatile(
      "mma.sync.aligned.m16n8k16.row.col.f32.f16.f16.f32 "
      "{%0,%1,%2,%3}, {%4,%5,%6,%7}, {%8,%9}, {%0,%1,%2,%3};"
      : "+f"(c[0]), "+f"(c[1]), "+f"(c[2]), "+f"(c[3])
      : "r"(a[0]), "r"(a[1]), "r"(a[2]), "r"(a[3]), "r"(b[0]), "r"(b[1]));
}
__device__ __forceinline__ uint32_t smem_u32(const void* p) {
  uint32_t a;
  asm("{ .reg .u64 t; cvta.to.shared.u64 t, %1; cvt.u32.u64 %0, t; }" : "=r"(a) : "l"(p));
  return a;
}
// fp32x4 -> fp16x4 (RN)
__device__ __forceinline__ uint2 cvt4h(float4 v) {
  __half2 h0 = __floats2half2_rn(v.x, v.y);
  __half2 h1 = __floats2half2_rn(v.z, v.w);
  uint2 h;
  h.x = *(uint32_t*)&h0;
  h.y = *(uint32_t*)&h1;
  return h;
}

// ===========================================================================
// GEMM1: P[s][q] = leakyrelu( sum_d ctx[s][d]*qry[q][d] ), fp16 x fp16 / fp32.
// m=s (A=ctx), n=q (B=qry), k=d. CTA 128x128, K-chunk 32, 8 warps (2m x 4n).
// fp16 double-buffered smem, one __syncthreads per chunk, reg prefetch.
// Epilogue accumulates per-row sum of leaky^2 into g_part (deterministic).
// ===========================================================================
#define P1 40  // smem row stride (half)

__global__ __launch_bounds__(256, 2) void k_scores_mma(
    const float* __restrict__ qry, const float* __restrict__ ctx,
    float* __restrict__ P) {
  __shared__ __align__(16) __half sAh[2][128 * P1];
  __shared__ __align__(16) __half sBh[2][128 * P1];
  __shared__ float sred[4][128];

  const int t = threadIdx.x, w = t >> 5, lane = t & 31;
  const int b = blockIdx.z, qblk = blockIdx.x, q0 = qblk * 128, s0 = blockIdx.y * 128;
  const int warp_m = w >> 2, warp_n = w & 3;

  const int lr = lane >> 3, lc8 = lane & 7;
  const float* Abase = ctx + ((size_t)(b * NS + s0)) * ND;  // rows = s
  const float* Bbase = qry + ((size_t)(b * NQ + q0)) * ND;  // rows = q

  // ldmatrix lane addressing (non-trans) — verified mapping
  const int g = lane >> 3, r8 = lane & 7;
  const int a_row = (g & 1) * 8 + r8, a_col = (g >> 1) * 8;
  const int b_row = (g >> 1) * 8 + r8, b_col = (g & 1) * 8;

  float acc[4][4][4];
#pragma unroll
  for (int i = 0; i < 4; i++)
#pragma unroll
    for (int j = 0; j < 4; j++)
#pragma unroll
      for (int k = 0; k < 4; k++) acc[i][j][k] = 0.0f;

  float4 stA[4], stB[4];
  const int col = lc8 * 4;
#pragma unroll
  for (int r4 = 0; r4 < 4; r4++) {
    const int row = r4 * 32 + w * 4 + lr;
    stA[r4] = *(const float4*)(Abase + (size_t)row * ND + col);
    stB[r4] = *(const float4*)(Bbase + (size_t)row * ND + col);
  }

  const int NCH = ND / 32;  // 32 chunks
  for (int c = 0; c < NCH; c++) {
    const int buf = c & 1;
#pragma unroll
    for (int r4 = 0; r4 < 4; r4++) {
      const int row = r4 * 32 + w * 4 + lr;
      *(uint2*)&sAh[buf][row * P1 + col] = cvt4h(stA[r4]);
      *(uint2*)&sBh[buf][row * P1 + col] = cvt4h(stB[r4]);
    }
    __syncthreads();  // only sync per chunk (double buffer)

    if (c + 1 < NCH) {  // prefetch next chunk into regs; hidden by mma
      const int kc = (c + 1) * 32;
#pragma unroll
      for (int r4 = 0; r4 < 4; r4++) {
        const int row = r4 * 32 + w * 4 + lr;
        stA[r4] = *(const float4*)(Abase + (size_t)row * ND + kc + col);
        stB[r4] = *(const float4*)(Bbase + (size_t)row * ND + kc + col);
      }
    }

    const uint32_t aH = smem_u32(sAh[buf]);
    const uint32_t bH = smem_u32(sBh[buf]);
#pragma unroll
    for (int kk = 0; kk < 32; kk += 16) {
      uint32_t bq[2][4];
#pragma unroll
      for (int np = 0; np < 2; np++) {
        const uint32_t off = ((warp_n * 32 + np * 16 + b_row) * P1 + kk + b_col) * 2;
        ldsm4(bq[np], bH + off);
      }
#pragma unroll
      for (int mi = 0; mi < 4; mi++) {
        uint32_t ah[4];
        const uint32_t off = ((warp_m * 64 + mi * 16 + a_row) * P1 + kk + a_col) * 2;
        ldsm4(ah, aH + off);
#pragma unroll
        for (int nt = 0; nt < 4; nt++) {
          mma16816(acc[mi][nt], ah, &bq[nt >> 1][(nt & 1) * 2]);
        }
      }
    }
  }

  // epilogue: leaky relu, write P[s][q], accumulate row sums of squares
  const int gm = lane >> 2, tg = lane & 3;
  float* Pb = P + (size_t)b * NS * NQ;
  float rsum[4][2];
#pragma unroll
  for (int mi = 0; mi < 4; mi++) {
    rsum[mi][0] = 0.0f;
    rsum[mi][1] = 0.0f;
    const int sg = s0 + warp_m * 64 + mi * 16 + gm;
#pragma unroll
    for (int nt = 0; nt < 4; nt++) {
      const int qg = q0 + warp_n * 32 + nt * 8 + tg * 2;
      float* c = acc[mi][nt];
      float2 v0 = make_float2(c[0] > 0.f ? c[0] : SLOPE * c[0],
                              c[1] > 0.f ? c[1] : SLOPE * c[1]);
      float2 v1 = make_float2(c[2] > 0.f ? c[2] : SLOPE * c[2],
                              c[3] > 0.f ? c[3] : SLOPE * c[3]);
      *(float2*)(Pb + (size_t)sg * NQ + qg) = v0;
      *(float2*)(Pb + (size_t)(sg + 8) * NQ + qg) = v1;
      rsum[mi][0] += v0.x * v0.x + v0.y * v0.y;
      rsum[mi][1] += v1.x * v1.x + v1.y * v1.y;
    }
  }
  // reduce over tg (4 lanes share a row)
#pragma unroll
  for (int mi = 0; mi < 4; mi++) {
#pragma unroll
    for (int h = 0; h < 2; h++) {
      float s = rsum[mi][h];
      s += __shfl_xor_sync(0xffffffffu, s, 1);
      s += __shfl_xor_sync(0xffffffffu, s, 2);
      if (tg == 0) sred[warp_n][warp_m * 64 + mi * 16 + h * 8 + gm] = s;
    }
  }
  __syncthreads();
  if (t < 128) {
    float s = sred[0][t] + sred[1][t] + sred[2][t] + sred[3][t];
    g_part[qblk][(size_t)b * NS + s0 + t] = s;
  }
}

// ===========================================================================
// GEMM2: W[q][d] = sum_s attn[s][q]*ctx[s][d], fp16 x fp16 / fp32.
// m=q (A = g_ah fp16, pre-converted by k_final, ldsm.trans),
// n=d (B = ctx fp32 -> cvt, ldsm.trans), k=s. Double-buffered, one sync/chunk.
// ===========================================================================
#define P2 136  // smem row stride (half)

__global__ __launch_bounds__(256, 2) void k_weighted_mma(
    const float* __restrict__ ctx, float* __restrict__ W) {
  __shared__ __align__(16) __half sAh[2][32 * P2];
  __shared__ __align__(16) __half sBh[2][32 * P2];

  const int t = threadIdx.x, w = t >> 5, lane = t & 31;
  const int b = blockIdx.z, d0 = blockIdx.x * 128, q0 = blockIdx.y * 128;
  const int warp_m = w >> 2, warp_n = w & 3;

  const int lr = lane >> 3, lc8 = lane & 7;
  const __half* Ab = g_ah + (size_t)b * NS * NQ;
  const float* Bb = ctx + (size_t)b * NS * ND;

  // ldmatrix.trans lane addressing — verified mapping
  const int g = lane >> 3, r8 = lane & 7;
  const int a_k = (g >> 1) * 8 + r8, a_m = (g & 1) * 8;
  const int b_k = (g & 1) * 8 + r8, b_n = (g >> 1) * 8;

  float acc[4][4][4];
#pragma unroll
  for (int i = 0; i < 4; i++)
#pragma unroll
    for (int j = 0; j < 4; j++)
#pragma unroll
      for (int k = 0; k < 4; k++) acc[i][j][k] = 0.0f;

  uint2 stA[4];
  float4 stB[4];
  const int row = w * 4 + lr;  // 0..31
#pragma unroll
  for (int cr = 0; cr < 4; cr++) {
    const int col = cr * 32 + lc8 * 4;
    stA[cr] = *(const uint2*)(Ab + (size_t)row * NQ + q0 + col);
    stB[cr] = *(const float4*)(Bb + (size_t)row * ND + d0 + col);
  }

  const int NCH = NS / 32;  // 16 chunks
  for (int c = 0; c < NCH; c++) {
    const int buf = c & 1;
#pragma unroll
    for (int cr = 0; cr < 4; cr++) {
      const int col = cr * 32 + lc8 * 4;
      *(uint2*)&sAh[buf][row * P2 + col] = stA[cr];
      *(uint2*)&sBh[buf][row * P2 + col] = cvt4h(stB[cr]);
    }
    __syncthreads();

    if (c + 1 < NCH) {
      const int sc = (c + 1) * 32;
#pragma unroll
      for (int cr = 0; cr < 4; cr++) {
        const int col = cr * 32 + lc8 * 4;
        stA[cr] = *(const uint2*)(Ab + (size_t)(sc + row) * NQ + q0 + col);
        stB[cr] = *(const float4*)(Bb + (size_t)(sc + row) * ND + d0 + col);
      }
    }

    const uint32_t aH = smem_u32(sAh[buf]);
    const uint32_t bH = smem_u32(sBh[buf]);
#pragma unroll
    for (int kk = 0; kk < 32; kk += 16) {
      uint32_t bq[2][4];
#pragma unroll
      for (int np = 0; np < 2; np++) {
        const uint32_t off = ((kk + b_k) * P2 + warp_n * 32 + np * 16 + b_n) * 2;
        ldsm4t(bq[np], bH + off);
      }
#pragma unroll
      for (int mi = 0; mi < 4; mi++) {
        uint32_t ah[4];
        const uint32_t off = ((kk + a_k) * P2 + warp_m * 64 + mi * 16 + a_m) * 2;
        ldsm4t(ah, aH + off);
#pragma unroll
        for (int nt = 0; nt < 4; nt++) {
          mma16816(acc[mi][nt], ah, &bq[nt >> 1][(nt & 1) * 2]);
        }
      }
    }
  }

  const int gm = lane >> 2, tg = lane & 3;
  float* Wb = W + (size_t)b * NQ * ND;
#pragma unroll
  for (int mi = 0; mi < 4; mi++) {
    const int qg = q0 + warp_m * 64 + mi * 16 + gm;
#pragma unroll
    for (int nt = 0; nt < 4; nt++) {
      const int dg = d0 + warp_n * 32 + nt * 8 + tg * 2;
      float* c = acc[mi][nt];
      *(float2*)(Wb + (size_t)qg * ND + dg) = make_float2(c[0], c[1]);
      *(float2*)(Wb + (size_t)(qg + 8) * ND + dg) = make_float2(c[2], c[3]);
    }
  }
}

// ---------------------------------------------------------------------------
// Softmax chain: k_denom fuses the partial-norm combine (writes g_invnorm)
// ---------------------------------------------------------------------------
__global__ __launch_bounds__(256) void k_denom(const float* __restrict__ P) {
  __shared__ float siv[NS];
  const int b = blockIdx.x;
  const int q = threadIdx.x;
  for (int s = q; s < NS; s += 256) {
    float v = 1.0f / (sqrtf(g_part[0][(size_t)b * NS + s] +
                            g_part[1][(size_t)b * NS + s]) + EPS);
    siv[s] = v;
    g_invnorm[(size_t)b * NS + s] = v;
  }
  __syncthreads();
  const float* Pb = P + (size_t)b * NS * NQ + q;
  float d0 = 0.f, d1 = 0.f, d2 = 0.f, d3 = 0.f;
#pragma unroll 4
  for (int s = 0; s < NS; s += 4) {
    d0 += __expf(SMOOTH * Pb[(size_t)(s + 0) * NQ] * siv[s + 0]);
    d1 += __expf(SMOOTH * Pb[(size_t)(s + 1) * NQ] * siv[s + 1]);
    d2 += __expf(SMOOTH * Pb[(size_t)(s + 2) * NQ] * siv[s + 2]);
    d3 += __expf(SMOOTH * Pb[(size_t)(s + 3) * NQ] * siv[s + 3]);
  }
  g_invden[b * NQ + q] = 1.0f / (d0 + d1 + d2 + d3);
}

// finalize attn in place (fp32 attnT output) AND emit fp16 copy for GEMM2
__global__ __launch_bounds__(256) void k_final(float* __restrict__ P) {
  const size_t idx4 = (size_t)blockIdx.x * blockDim.x + threadIdx.x;
  const int q4 = (int)(idx4 & 63);
  const size_t row = idx4 >> 6;
  const int b = (int)(row >> 9);
  const float inv = g_invnorm[row];
  const float* id = g_invden + b * NQ + q4 * 4;
  float4 v = ((float4*)P)[idx4];
  v.x = __expf(SMOOTH * v.x * inv) * id[0];
  v.y = __expf(SMOOTH * v.y * inv) * id[1];
  v.z = __expf(SMOOTH * v.z * inv) * id[2];
  v.w = __expf(SMOOTH * v.w * inv) * id[3];
  ((float4*)P)[idx4] = v;
  ((uint2*)g_ah)[idx4] = cvt4h(v);  // same rounding GEMM2 used before
}

// ---------------------------------------------------------------------------
// d_out = [ weighted (B,Q,D) | attnT (B,S,Q) ]; attnT region doubles as
// scratch for the score matrix through the softmax chain.
// ---------------------------------------------------------------------------
extern "C" void kernel_launch(void* const* d_in, const int* in_sizes, int n_in,
                              void* d_out, int out_size) {
  const float* qry = (const float*)d_in[0];  // (B,Q,D)
  const float* ctx = (const float*)d_in[1];  // (B,S,D)
  float* W = (float*)d_out;                         // (B,Q,D)
  float* P = (float*)d_out + (size_t)NB * NQ * ND;  // (B,S,Q)

  {
    dim3 g(NQ / 128, NS / 128, NB);  // (2, 4, 256)
    k_scores_mma<<<g, 256>>>(qry, ctx, P);
  }
  k_denom<<<NB, 256>>>(P);
  k_final<<<(size_t)NB * NS * NQ / 4 / 256, 256>>>(P);
  {
    dim3 g(ND / 128, NQ / 128, NB);  // (8, 2, 256)
    k_weighted_mma<<<g, 256>>>(ctx, W);
  }
}